// round 6
// baseline (speedup 1.0000x reference)
#include <cuda_runtime.h>
#include <math.h>

#define Bn   16
#define Tn   750
#define Fd   4096
#define Cd   20
#define KS   93
#define NROW (Bn*Tn)          // 12000

// ---- output layout (float elements) ----
#define OFF_SACT 0
#define OFF_SBKG 320
#define OFF_FACT 640
#define OFF_FBKG 6095488
#define OFF_FEAT 12190336
#define OFF_CSM  61342336

// ---- device scratch (no allocations allowed) ----
__device__ float g_cas[NROW*Cd];     // raw cas scores
__device__ float g_mag[NROW];        // ||x|| per row
__device__ int   g_idx_act[Bn*KS];
__device__ int   g_idx_bkg[Bn*KS];
__device__ float g_sact[Bn*Cd];      // pre-softmax topk means

// ============================================================================
// K1: per-row fused pass. 750 blocks x 512 threads, 16 rows/block.
//  - cas = (x*mask) @ W^T   (W chunks staged in smem, 4-row register blocking)
//  - mag = ||x||  (per-thread f32 partials, fp64 cross-thread reduction)
//  - features out = x
//  - cas_softmax out = softmax_C(cas)
// smem: W chunk 81920B | part 5120B | sqp 512B | cass 1280B  = 88832B
// ============================================================================
__global__ __launch_bounds__(512,1) void k1_main(
    const float4* __restrict__ x4, const float* __restrict__ W,
    const float4* __restrict__ m4, float4* __restrict__ feat4,
    float* __restrict__ cas_sm)
{
    extern __shared__ char smraw[];
    float4* smw  = (float4*)smraw;                          // [Cd*256] float4
    float*  part = (float*) (smraw + 81920);                // [16][Cd][4]
    double* sqp  = (double*)(smraw + 81920 + 5120);         // [16][4]
    float*  cass = (float*) (smraw + 81920 + 5120 + 512);   // [16][Cd]

    const int tid  = threadIdx.x;
    const int row0 = blockIdx.x * 16;
    const int fl   = tid & 127;     // f-lane within 128
    const int rg   = tid >> 7;      // row group 0..3
    const int rbase = row0 + rg * 4;

    float acc[Cd][4];
    #pragma unroll
    for (int c = 0; c < Cd; c++)
        #pragma unroll
        for (int r = 0; r < 4; r++) acc[c][r] = 0.f;
    float ssq[4] = {0.f, 0.f, 0.f, 0.f};

    const float4* W4 = (const float4*)W;

    for (int ch = 0; ch < 4; ch++) {
        // cooperative load of W chunk: Cd x 256 float4
        for (int t = tid; t < Cd * 256; t += 512) {
            int c = t >> 8, p = t & 255;
            smw[t] = __ldg(W4 + c * 1024 + ch * 256 + p);
        }
        __syncthreads();

        #pragma unroll
        for (int fo = 0; fo < 2; fo++) {
            const int fi = ch * 256 + fo * 128 + fl;   // float4 index in row
            float4 xm[4];
            #pragma unroll
            for (int r = 0; r < 4; r++) {
                int base = (rbase + r) * 1024 + fi;
                float4 xv = __ldg(x4 + base);
                float4 mv = __ldg(m4 + base);
                feat4[base] = xv;
                ssq[r] += xv.x*xv.x + xv.y*xv.y + xv.z*xv.z + xv.w*xv.w;
                xm[r].x = xv.x * mv.x; xm[r].y = xv.y * mv.y;
                xm[r].z = xv.z * mv.z; xm[r].w = xv.w * mv.w;
            }
            const float4* wrow = smw + fo * 128 + fl;
            #pragma unroll
            for (int c = 0; c < Cd; c++) {
                float4 w = wrow[c * 256];
                #pragma unroll
                for (int r = 0; r < 4; r++) {
                    acc[c][r] = fmaf(w.x, xm[r].x, acc[c][r]);
                    acc[c][r] = fmaf(w.y, xm[r].y, acc[c][r]);
                    acc[c][r] = fmaf(w.z, xm[r].z, acc[c][r]);
                    acc[c][r] = fmaf(w.w, xm[r].w, acc[c][r]);
                }
            }
        }
        __syncthreads();
    }

    // ---- reductions ----
    const int lane = tid & 31;
    const int ww   = (tid >> 5) & 3;   // warp within row group
    #pragma unroll
    for (int c = 0; c < Cd; c++) {
        #pragma unroll
        for (int r = 0; r < 4; r++) {
            float v = acc[c][r];
            v += __shfl_down_sync(0xffffffffu, v, 16);
            v += __shfl_down_sync(0xffffffffu, v, 8);
            v += __shfl_down_sync(0xffffffffu, v, 4);
            v += __shfl_down_sync(0xffffffffu, v, 2);
            v += __shfl_down_sync(0xffffffffu, v, 1);
            if (lane == 0) part[((rg * 4 + r) * Cd + c) * 4 + ww] = v;
        }
    }
    #pragma unroll
    for (int r = 0; r < 4; r++) {
        double d = (double)ssq[r];
        d += __shfl_down_sync(0xffffffffu, d, 16);
        d += __shfl_down_sync(0xffffffffu, d, 8);
        d += __shfl_down_sync(0xffffffffu, d, 4);
        d += __shfl_down_sync(0xffffffffu, d, 2);
        d += __shfl_down_sync(0xffffffffu, d, 1);
        if (lane == 0) sqp[(rg * 4 + r) * 4 + ww] = d;
    }
    __syncthreads();

    if (tid < 16 * Cd) {
        int r = tid / Cd, c = tid % Cd;
        const float* p = part + (r * Cd + c) * 4;
        float v = p[0] + p[1] + p[2] + p[3];
        g_cas[(row0 + r) * Cd + c] = v;
        cass[r * Cd + c] = v;
    }
    if (tid < 16) {
        double s = sqp[tid * 4] + sqp[tid * 4 + 1] + sqp[tid * 4 + 2] + sqp[tid * 4 + 3];
        g_mag[row0 + tid] = (float)sqrt(s);
    }
    __syncthreads();

    if (tid < 16) {
        int row = row0 + tid;
        float m = -1e30f;
        #pragma unroll
        for (int c = 0; c < Cd; c++) m = fmaxf(m, cass[tid * Cd + c]);
        float e[Cd]; float s = 0.f;
        #pragma unroll
        for (int c = 0; c < Cd; c++) { e[c] = expf(cass[tid * Cd + c] - m); s += e[c]; }
        float inv = 1.f / s;
        #pragma unroll
        for (int c = 0; c < Cd; c++) cas_sm[row * Cd + c] = e[c] * inv;
    }
}

// ============================================================================
// K2: per-batch ordered top-93 indices via exact rank counting (stable,
// matching jax.lax.top_k tie-break: lower index first).
// grid (6,16), 128 threads; each block handles 125 candidate positions.
// ============================================================================
__global__ void k2_topk(const float* __restrict__ sel)
{
    const int chunk = blockIdx.x, b = blockIdx.y, tid = threadIdx.x;
    __shared__ float md[Tn], mrd[Tn];
    __shared__ float wmax[4];

    float lmax = -1e30f;
    for (int i = tid; i < Tn; i += 128) {
        float m = g_mag[b * Tn + i];
        float s = sel[b * Tn + i];
        md[i] = m; mrd[i] = s;
        lmax = fmaxf(lmax, m);
    }
    for (int o = 16; o > 0; o >>= 1) lmax = fmaxf(lmax, __shfl_down_sync(0xffffffffu, lmax, o));
    if ((tid & 31) == 0) wmax[tid >> 5] = lmax;
    __syncthreads();
    float maxm = fmaxf(fmaxf(wmax[0], wmax[1]), fmaxf(wmax[2], wmax[3]));
    for (int i = tid; i < Tn; i += 128) {
        float m = md[i], s = mrd[i];
        md[i]  = m * s;
        mrd[i] = (maxm - m) * s;
    }
    __syncthreads();

    const int i = chunk * 125 + tid;
    if (tid < 125) {
        float v1 = md[i], v2 = mrd[i];
        int r1 = 0, r2 = 0;
        #pragma unroll 5
        for (int j = 0; j < Tn; j++) {
            float u1 = md[j];
            r1 += (int)(u1 > v1) + (int)((u1 == v1) & (j < i));
            float u2 = mrd[j];
            r2 += (int)(u2 > v2) + (int)((u2 == v2) & (j < i));
        }
        if (r1 < KS) g_idx_act[b * KS + r1] = i;
        if (r2 < KS) g_idx_bkg[b * KS + r2] = i;
    }
}

// ============================================================================
// K3: score_act pre-softmax means: per (b,c), exact sum of top-93 cas values
// via 32-step radix select on order-preserving uint keys. grid (20,16), 256 thr.
// ============================================================================
__global__ void k3_scoreact()
{
    const int c = blockIdx.x, b = blockIdx.y, tid = threadIdx.x;
    __shared__ float    col[Tn];
    __shared__ unsigned key[Tn];
    __shared__ int      wsum[8];
    __shared__ float    wsumf[8];
    __shared__ int      stot;

    for (int i = tid; i < Tn; i += 256) {
        float v = g_cas[(b * Tn + i) * Cd + c];
        col[i] = v;
        unsigned u = __float_as_uint(v);
        key[i] = (u & 0x80000000u) ? ~u : (u | 0x80000000u);
    }
    __syncthreads();

    unsigned prefix = 0u;
    for (int bit = 31; bit >= 0; --bit) {
        unsigned cand = prefix | (1u << bit);
        int cnt = 0;
        for (int i = tid; i < Tn; i += 256) cnt += (int)(key[i] >= cand);
        cnt = (int)__reduce_add_sync(0xffffffffu, (unsigned)cnt);
        if ((tid & 31) == 0) wsum[tid >> 5] = cnt;
        __syncthreads();
        if (tid == 0) { int t = 0; for (int w = 0; w < 8; w++) t += wsum[w]; stot = t; }
        __syncthreads();
        if (stot >= KS) prefix = cand;
    }
    // prefix == key of the 93rd-largest value
    float thr;
    { unsigned u = prefix; u = (u & 0x80000000u) ? (u & 0x7fffffffu) : ~u; thr = __uint_as_float(u); }

    int cg = 0; float s = 0.f;
    for (int i = tid; i < Tn; i += 256)
        if (key[i] > prefix) { cg++; s += col[i]; }
    cg = (int)__reduce_add_sync(0xffffffffu, (unsigned)cg);
    for (int o = 16; o > 0; o >>= 1) s += __shfl_down_sync(0xffffffffu, s, o);
    if ((tid & 31) == 0) { wsum[tid >> 5] = cg; wsumf[tid >> 5] = s; }
    __syncthreads();
    if (tid == 0) {
        int Ct = 0; float S = 0.f;
        for (int w = 0; w < 8; w++) { Ct += wsum[w]; S += wsumf[w]; }
        g_sact[b * Cd + c] = (S + (float)(KS - Ct) * thr) * (1.f / (float)KS);
    }
}

// ============================================================================
// K4: score_bkg (mean of cas over idx_bkg rows) + both softmaxes. grid 16.
// ============================================================================
__global__ void k4_scores(float* __restrict__ score_act, float* __restrict__ score_bkg)
{
    const int b = blockIdx.x, tid = threadIdx.x;
    __shared__ float red[12 * Cd];
    __shared__ float sb[Cd], sa[Cd], eb[Cd], ea[Cd];

    if (tid < 240) {
        int c = tid % Cd, p = tid / Cd;
        float s = 0.f;
        for (int k = p; k < KS; k += 12) {
            int t = g_idx_bkg[b * KS + k];
            s += g_cas[(b * Tn + t) * Cd + c];
        }
        red[p * Cd + c] = s;
    }
    __syncthreads();
    if (tid < Cd) {
        float s = 0.f;
        for (int p = 0; p < 12; p++) s += red[p * Cd + tid];
        sb[tid] = s * (1.f / (float)KS);
        sa[tid] = g_sact[b * Cd + tid];
    }
    __syncthreads();
    if (tid < Cd) {
        float mb = -1e30f, ma = -1e30f;
        for (int j = 0; j < Cd; j++) { mb = fmaxf(mb, sb[j]); ma = fmaxf(ma, sa[j]); }
        eb[tid] = expf(sb[tid] - mb);
        ea[tid] = expf(sa[tid] - ma);
    }
    __syncthreads();
    if (tid < Cd) {
        float Sb = 0.f, Sa = 0.f;
        for (int j = 0; j < Cd; j++) { Sb += eb[j]; Sa += ea[j]; }
        score_bkg[b * Cd + tid] = eb[tid] / Sb;
        score_act[b * Cd + tid] = ea[tid] / Sa;
    }
}

// ============================================================================
// K5: gather feat_act / feat_bkg rows. grid (93,16,2), 256 threads.
// ============================================================================
__global__ void k5_gather(const float4* __restrict__ x4, float4* __restrict__ out4)
{
    const int k = blockIdx.x, b = blockIdx.y;
    const int* idx = blockIdx.z ? g_idx_bkg : g_idx_act;
    const int t = idx[b * KS + k];
    const float4* s = x4 + (long)(b * Tn + t) * 1024;
    float4* d = out4 + (blockIdx.z ? (OFF_FBKG / 4) : (OFF_FACT / 4)) + (long)(b * KS + k) * 1024;
    for (int i = threadIdx.x; i < 1024; i += 256) d[i] = s[i];
}

// ============================================================================
extern "C" void kernel_launch(void* const* d_in, const int* in_sizes, int n_in,
                              void* d_out, int out_size)
{
    const float* x    = (const float*)d_in[0];
    const float* W    = (const float*)d_in[1];
    const float* mask = (const float*)d_in[2];
    const float* sel  = (const float*)d_in[3];
    float* out = (float*)d_out;

    cudaFuncSetAttribute(k1_main, cudaFuncAttributeMaxDynamicSharedMemorySize, 88832);

    k1_main<<<NROW / 16, 512, 88832>>>((const float4*)x, W, (const float4*)mask,
                                       (float4*)(out + OFF_FEAT), out + OFF_CSM);
    k2_topk<<<dim3(6, Bn), 128>>>(sel);
    k3_scoreact<<<dim3(Cd, Bn), 256>>>();
    k4_scores<<<Bn, 256>>>(out + OFF_SACT, out + OFF_SBKG);
    k5_gather<<<dim3(KS, Bn, 2), 256>>>((const float4*)x, (float4*)out);
}